// round 6
// baseline (speedup 1.0000x reference)
#include <cuda_runtime.h>
#include <math.h>
#include <stdint.h>

#define NTOK   2048
#define DMODEL 256
#define DFF    1024
#define NHEAD  8
#define DHEAD  32
#define KWIN   5
#define NNBR   125   // 5*5*5

// ---------------- scratch (device globals; no allocations allowed) ----------
__device__ float g_q [NTOK * DMODEL];
__device__ float g_k [NTOK * DMODEL];
__device__ float g_v [NTOK * DMODEL];
__device__ float g_at[NTOK * DMODEL];
__device__ float g_h [NTOK * DMODEL];
__device__ float g_fa[NTOK * DFF];
__device__ float g_rs1[NTOK];
__device__ float g_ssp[8 * NTOK];   // per-row sumsq partials of h (8 col-slices)

// ---------------- helpers ----------------------------------------------------
__device__ __forceinline__ void mma_tf32(float d[4], const uint32_t a[4], const uint32_t b[2]) {
    asm volatile(
        "mma.sync.aligned.m16n8k8.row.col.f32.tf32.tf32.f32 "
        "{%0,%1,%2,%3},{%4,%5,%6,%7},{%8,%9},{%0,%1,%2,%3};"
        : "+f"(d[0]), "+f"(d[1]), "+f"(d[2]), "+f"(d[3])
        : "r"(a[0]), "r"(a[1]), "r"(a[2]), "r"(a[3]), "r"(b[0]), "r"(b[1]));
}

// ---------------- RMS scale: one warp per token ------------------------------
__global__ __launch_bounds__(256) void rms_scale_k(const float* __restrict__ x,
                                                   float* __restrict__ rscale) {
    const int warp = threadIdx.x >> 5;
    const int lane = threadIdx.x & 31;
    const int token = blockIdx.x * 8 + warp;
    const float4 a = *(const float4*)&x[(size_t)token * DMODEL + lane * 4];
    const float4 b = *(const float4*)&x[(size_t)token * DMODEL + 128 + lane * 4];
    float s = a.x * a.x + a.y * a.y + a.z * a.z + a.w * a.w
            + b.x * b.x + b.y * b.y + b.z * b.z + b.w * b.w;
    #pragma unroll
    for (int o = 16; o; o >>= 1) s += __shfl_xor_sync(0xffffffffu, s, o);
    if (lane == 0) rscale[token] = rsqrtf(s * (1.0f / DMODEL) + 1e-6f);
}

// ---------------- direct-LDG TF32 GEMM: no smem, fragments from L1 -----------
// Block 32x64 tile, 128 threads = 4 warps (2x2), warp tile 16x32.
// Optional fused RMSNorm on A (rs,nw). Optional sumsq-partial output (ssp).
// blockIdx.z selects among up to 3 (B, bias, C) triples (QKV fusion).
__global__ __launch_bounds__(128) void gemm_d(
    const float* __restrict__ A,
    const float* __restrict__ rs, const float* __restrict__ nw,
    const float* __restrict__ B0, const float* __restrict__ B1, const float* __restrict__ B2,
    const float* __restrict__ bias0, const float* __restrict__ bias1, const float* __restrict__ bias2,
    const float* __restrict__ res,
    float* __restrict__ C0, float* __restrict__ C1, float* __restrict__ C2,
    float* __restrict__ ssp,
    int N, int K) {

    const int z = blockIdx.z;
    const float* B    = (z == 0) ? B0    : (z == 1) ? B1    : B2;
    const float* bias = (z == 0) ? bias0 : (z == 1) ? bias1 : bias2;
    float*       C    = (z == 0) ? C0    : (z == 1) ? C1    : C2;

    const int tid  = threadIdx.x;
    const int warp = tid >> 5;
    const int lane = tid & 31;
    const int g    = lane >> 2;
    const int tig  = lane & 3;
    const int warpRow = (warp & 1) * 16;
    const int warpCol = (warp >> 1) * 32;
    const int bm = blockIdx.y * 32;
    const int bn = blockIdx.x * 64;

    const int r0 = bm + warpRow + g;
    const int r1 = r0 + 8;
    const float sc0 = rs ? rs[r0] : 1.f;
    const float sc1 = rs ? rs[r1] : 1.f;

    const float* Ap0 = A + (size_t)r0 * K + tig;
    const float* Ap1 = A + (size_t)r1 * K + tig;
    const float* Bp  = B + (size_t)tig * N + bn + warpCol + g;

    float acc[4][4];
    #pragma unroll
    for (int nt = 0; nt < 4; nt++)
        #pragma unroll
        for (int i = 0; i < 4; i++) acc[nt][i] = 0.f;

    const int nsteps = K >> 3;
    #pragma unroll 4
    for (int s = 0; s < nsteps; s++) {
        const int k0 = s << 3;
        float a0 = Ap0[k0], a1 = Ap1[k0], a2 = Ap0[k0 + 4], a3 = Ap1[k0 + 4];
        uint32_t b[4][2];
        #pragma unroll
        for (int nt = 0; nt < 4; nt++) {
            b[nt][0] = __float_as_uint(Bp[(size_t)k0 * N + nt * 8]);
            b[nt][1] = __float_as_uint(Bp[(size_t)(k0 + 4) * N + nt * 8]);
        }
        if (rs) {
            const float w0 = nw[k0 + tig], w1 = nw[k0 + 4 + tig];
            a0 *= sc0 * w0; a1 *= sc1 * w0; a2 *= sc0 * w1; a3 *= sc1 * w1;
        }
        uint32_t ua[4] = {__float_as_uint(a0), __float_as_uint(a1),
                          __float_as_uint(a2), __float_as_uint(a3)};
        #pragma unroll
        for (int nt = 0; nt < 4; nt++) mma_tf32(acc[nt], ua, b[nt]);
    }

    // epilogue (+optional per-row sumsq partials for the next rmsnorm)
    float s0 = 0.f, s1 = 0.f;
    #pragma unroll
    for (int nt = 0; nt < 4; nt++) {
        const int col = bn + warpCol + nt * 8 + 2 * tig;
        float b0 = 0.f, b1 = 0.f;
        if (bias) { b0 = bias[col]; b1 = bias[col + 1]; }
        float2 o0 = make_float2(acc[nt][0] + b0, acc[nt][1] + b1);
        float2 o1 = make_float2(acc[nt][2] + b0, acc[nt][3] + b1);
        if (res) {
            const float2 q0 = *(const float2*)&res[(size_t)r0 * N + col];
            const float2 q1 = *(const float2*)&res[(size_t)r1 * N + col];
            o0.x += q0.x; o0.y += q0.y;
            o1.x += q1.x; o1.y += q1.y;
        }
        s0 += o0.x * o0.x + o0.y * o0.y;
        s1 += o1.x * o1.x + o1.y * o1.y;
        *(float2*)&C[(size_t)r0 * N + col] = o0;
        *(float2*)&C[(size_t)r1 * N + col] = o1;
    }
    if (ssp) {
        s0 += __shfl_xor_sync(0xffffffffu, s0, 1);
        s0 += __shfl_xor_sync(0xffffffffu, s0, 2);
        s1 += __shfl_xor_sync(0xffffffffu, s1, 1);
        s1 += __shfl_xor_sync(0xffffffffu, s1, 2);
        if (tig == 0) {
            const int p = blockIdx.x * 2 + (warp >> 1);   // 0..7 distinct col slices
            ssp[p * NTOK + r0] = s0;
            ssp[p * NTOK + r1] = s1;
        }
    }
}

// ---------------- direct-LDG gate GEMM: silu(A'@W1)*(A'@W2) ------------------
// A' = rmsnorm(A) with scale rebuilt from 8 sumsq partials. 32x64 tile.
__global__ __launch_bounds__(128) void gemm_gate_d(
    const float* __restrict__ A,
    const float* __restrict__ ssp, const float* __restrict__ nw,
    const float* __restrict__ W1, const float* __restrict__ W2,
    float* __restrict__ C, int N, int K) {

    const int tid  = threadIdx.x;
    const int warp = tid >> 5;
    const int lane = tid & 31;
    const int g    = lane >> 2;
    const int tig  = lane & 3;
    const int warpRow = (warp & 1) * 16;
    const int warpCol = (warp >> 1) * 32;
    const int bm = blockIdx.y * 32;
    const int bn = blockIdx.x * 64;

    const int r0 = bm + warpRow + g;
    const int r1 = r0 + 8;
    float ss0 = 0.f, ss1 = 0.f;
    #pragma unroll
    for (int p = 0; p < 8; p++) {
        ss0 += ssp[p * NTOK + r0];
        ss1 += ssp[p * NTOK + r1];
    }
    const float sc0 = rsqrtf(ss0 * (1.0f / DMODEL) + 1e-6f);
    const float sc1 = rsqrtf(ss1 * (1.0f / DMODEL) + 1e-6f);

    const float* Ap0 = A + (size_t)r0 * K + tig;
    const float* Ap1 = A + (size_t)r1 * K + tig;
    const float* B1p = W1 + (size_t)tig * N + bn + warpCol + g;
    const float* B2p = W2 + (size_t)tig * N + bn + warpCol + g;

    float acc1[4][4], acc2[4][4];
    #pragma unroll
    for (int nt = 0; nt < 4; nt++)
        #pragma unroll
        for (int i = 0; i < 4; i++) { acc1[nt][i] = 0.f; acc2[nt][i] = 0.f; }

    const int nsteps = K >> 3;
    #pragma unroll 4
    for (int s = 0; s < nsteps; s++) {
        const int k0 = s << 3;
        float a0 = Ap0[k0], a1 = Ap1[k0], a2 = Ap0[k0 + 4], a3 = Ap1[k0 + 4];
        uint32_t b1[4][2], b2[4][2];
        #pragma unroll
        for (int nt = 0; nt < 4; nt++) {
            b1[nt][0] = __float_as_uint(B1p[(size_t)k0 * N + nt * 8]);
            b1[nt][1] = __float_as_uint(B1p[(size_t)(k0 + 4) * N + nt * 8]);
            b2[nt][0] = __float_as_uint(B2p[(size_t)k0 * N + nt * 8]);
            b2[nt][1] = __float_as_uint(B2p[(size_t)(k0 + 4) * N + nt * 8]);
        }
        const float w0 = nw[k0 + tig], w1 = nw[k0 + 4 + tig];
        a0 *= sc0 * w0; a1 *= sc1 * w0; a2 *= sc0 * w1; a3 *= sc1 * w1;
        uint32_t ua[4] = {__float_as_uint(a0), __float_as_uint(a1),
                          __float_as_uint(a2), __float_as_uint(a3)};
        #pragma unroll
        for (int nt = 0; nt < 4; nt++) {
            mma_tf32(acc1[nt], ua, b1[nt]);
            mma_tf32(acc2[nt], ua, b2[nt]);
        }
    }

    #pragma unroll
    for (int nt = 0; nt < 4; nt++) {
        const int col = bn + warpCol + nt * 8 + 2 * tig;
        #pragma unroll
        for (int half = 0; half < 2; half++) {
            const int row = (half == 0) ? r0 : r1;
            const float a0 = acc1[nt][half * 2 + 0];
            const float a1 = acc1[nt][half * 2 + 1];
            float2 o;
            o.x = a0 / (1.f + __expf(-a0)) * acc2[nt][half * 2 + 0];
            o.y = a1 / (1.f + __expf(-a1)) * acc2[nt][half * 2 + 1];
            *(float2*)&C[(size_t)row * N + col] = o;
        }
    }
}

// ---------------- NA3D attention: smem-tiled ---------------------------------
__global__ __launch_bounds__(512) void na3d_k(
    const float* __restrict__ q, const float* __restrict__ k,
    const float* __restrict__ v, float* __restrict__ out) {

    __shared__ float smk[320 * 32];
    __shared__ int   nbase[128];

    const int tile = blockIdx.x;
    const int head = blockIdx.y;
    const int t  = tile >> 4;
    const int hh = (tile >> 2) & 3;
    const int ww = tile & 3;
    const int tile_h0 = hh * 4, tile_w0 = ww * 4;
    const int h_base = min(max(tile_h0 - 2, 0), 8);
    const int w_base = min(max(tile_w0 - 2, 0), 8);

    const int tid  = threadIdx.x;
    const int warp = tid >> 5;
    const int lane = tid & 31;
    const int g    = lane >> 3;
    const int sub  = lane & 7;

    if (tid < 128) {
        const int m = tid;
        int val;
        if (m < NNBR) {
            const int mt = m / 25;
            const int mh = (m / 5) % 5;
            const int mw = m % 5;
            val = (mt * 64 + mh * 8 + mw) | (mt << 16);
        } else {
            val = (-8) << 16;
        }
        nbase[tid] = val;
    }

    const int h = tile_h0 + (warp >> 2);
    const int w = tile_w0 + (warp & 3);
    const int token = (t * 16 + h) * 16 + w;
    const int hoff = min(max(h - 2, 0), 11) - h_base;
    const int woff = min(max(w - 2, 0), 11) - w_base;
    const int sbase = hoff * 8 + woff;

    #pragma unroll
    for (int j = 0; j < 5; j++) {
        const int c = tid + 512 * j;
        const int slot = c >> 3, s8 = c & 7;
        const int tl = slot >> 6, rem = slot & 63;
        const int tn = max(t - 4 + tl, 0);
        const int hn = h_base + (rem >> 3), wn = w_base + (rem & 7);
        const float4 kv = *(const float4*)&k[(size_t)((tn * 16 + hn) * 16 + wn) * DMODEL + head * DHEAD + s8 * 4];
        *(float4*)&smk[slot * 32 + s8 * 4] = kv;
    }
    const float4 q4 = *(const float4*)&q[(size_t)token * DMODEL + head * DHEAD + sub * 4];
    __syncthreads();

    float lg[32];
    const float scale = 0.17677669529663687f;
    #pragma unroll
    for (int i = 0; i < 32; i++) {
        const int m   = i * 4 + g;
        const int val = nbase[m];
        const int slot = (val & 0xFFFF) + sbase;
        const int mt   = val >> 16;
        const float4 kv = *(const float4*)&smk[slot * 32 + sub * 4];
        float d = q4.x * kv.x + q4.y * kv.y + q4.z * kv.z + q4.w * kv.w;
        d += __shfl_xor_sync(0xffffffffu, d, 1);
        d += __shfl_xor_sync(0xffffffffu, d, 2);
        d += __shfl_xor_sync(0xffffffffu, d, 4);
        lg[i] = (t - 4 + mt >= 0) ? d * scale : -INFINITY;
    }

    float mx = -INFINITY;
    #pragma unroll
    for (int i = 0; i < 32; i++) mx = fmaxf(mx, lg[i]);
    #pragma unroll
    for (int o = 16; o; o >>= 1) mx = fmaxf(mx, __shfl_xor_sync(0xffffffffu, mx, o));
    float sum = 0.f;
    #pragma unroll
    for (int i = 0; i < 32; i++) { lg[i] = __expf(lg[i] - mx); sum += lg[i]; }
    sum += __shfl_xor_sync(0xffffffffu, sum, 8);
    sum += __shfl_xor_sync(0xffffffffu, sum, 16);
    const float inv = 1.f / sum;

    __syncthreads();
    #pragma unroll
    for (int j = 0; j < 5; j++) {
        const int c = tid + 512 * j;
        const int slot = c >> 3, s8 = c & 7;
        const int tl = slot >> 6, rem = slot & 63;
        const int tn = max(t - 4 + tl, 0);
        const int hn = h_base + (rem >> 3), wn = w_base + (rem & 7);
        const float4 vv = *(const float4*)&v[(size_t)((tn * 16 + hn) * 16 + wn) * DMODEL + head * DHEAD + s8 * 4];
        *(float4*)&smk[slot * 32 + s8 * 4] = vv;
    }
    __syncthreads();

    float4 acc = make_float4(0.f, 0.f, 0.f, 0.f);
    #pragma unroll
    for (int i = 0; i < 32; i++) {
        const int m    = i * 4 + g;
        const int slot = (nbase[m] & 0xFFFF) + sbase;
        const float4 vv = *(const float4*)&smk[slot * 32 + sub * 4];
        const float p = lg[i];
        acc.x = fmaf(p, vv.x, acc.x);
        acc.y = fmaf(p, vv.y, acc.y);
        acc.z = fmaf(p, vv.z, acc.z);
        acc.w = fmaf(p, vv.w, acc.w);
    }
    #pragma unroll
    for (int o = 8; o <= 16; o <<= 1) {
        acc.x += __shfl_xor_sync(0xffffffffu, acc.x, o);
        acc.y += __shfl_xor_sync(0xffffffffu, acc.y, o);
        acc.z += __shfl_xor_sync(0xffffffffu, acc.z, o);
        acc.w += __shfl_xor_sync(0xffffffffu, acc.w, o);
    }
    if (g == 0) {
        float4 o4 = make_float4(acc.x * inv, acc.y * inv, acc.z * inv, acc.w * inv);
        *(float4*)&out[(size_t)token * DMODEL + head * DHEAD + sub * 4] = o4;
    }
}

// ---------------- launch ------------------------------------------------------
extern "C" void kernel_launch(void* const* d_in, const int* in_sizes, int n_in,
                              void* d_out, int out_size) {
    const float* x   = (const float*)d_in[0];
    const float* n1w = (const float*)d_in[1];
    const float* n2w = (const float*)d_in[2];
    const float* wq  = (const float*)d_in[3];
    const float* bq  = (const float*)d_in[4];
    const float* wk  = (const float*)d_in[5];
    const float* bk  = (const float*)d_in[6];
    const float* wv  = (const float*)d_in[7];
    const float* bv  = (const float*)d_in[8];
    const float* wo  = (const float*)d_in[9];
    const float* bo  = (const float*)d_in[10];
    const float* w1  = (const float*)d_in[11];
    const float* w2  = (const float*)d_in[12];
    const float* w3  = (const float*)d_in[13];
    float* out = (float*)d_out;

    float *p_q, *p_k, *p_v, *p_at, *p_h, *p_fa, *p_rs1, *p_ssp;
    cudaGetSymbolAddress((void**)&p_q,  g_q);
    cudaGetSymbolAddress((void**)&p_k,  g_k);
    cudaGetSymbolAddress((void**)&p_v,  g_v);
    cudaGetSymbolAddress((void**)&p_at, g_at);
    cudaGetSymbolAddress((void**)&p_h,  g_h);
    cudaGetSymbolAddress((void**)&p_fa, g_fa);
    cudaGetSymbolAddress((void**)&p_rs1, g_rs1);
    cudaGetSymbolAddress((void**)&p_ssp, g_ssp);

    const dim3 blk(128);

    // 1) rscale1 = rms scale of x
    rms_scale_k<<<NTOK / 8, 256>>>(x, p_rs1);

    // 2) q,k,v = rmsnorm(x) @ {wq,wk,wv} + bias
    gemm_d<<<dim3(DMODEL / 64, NTOK / 32, 3), blk>>>(
        x, p_rs1, n1w, wq, wk, wv, bq, bk, bv, nullptr,
        p_q, p_k, p_v, nullptr, DMODEL, DMODEL);

    // 3) neighborhood attention
    na3d_k<<<dim3(128, NHEAD), 512>>>(p_q, p_k, p_v, p_at);

    // 4) h = x + attn @ wo + bo   (+ per-row sumsq partials of h)
    gemm_d<<<dim3(DMODEL / 64, NTOK / 32, 1), blk>>>(
        p_at, nullptr, nullptr, wo, nullptr, nullptr, bo, nullptr, nullptr, x,
        p_h, nullptr, nullptr, p_ssp, DMODEL, DMODEL);

    // 5) fa = silu(rmsnorm(h)@w1) * (rmsnorm(h)@w2)  (rms scale from partials)
    gemm_gate_d<<<dim3(DFF / 64, NTOK / 32), blk>>>(
        p_h, p_ssp, n2w, w1, w2, p_fa, DFF, DMODEL);

    // 6) out = h + fa @ w3
    gemm_d<<<dim3(DMODEL / 64, NTOK / 32, 1), blk>>>(
        p_fa, nullptr, nullptr, w3, nullptr, nullptr, nullptr, nullptr, nullptr, p_h,
        out, nullptr, nullptr, nullptr, DMODEL, DFF);
}

// round 7
// speedup vs baseline: 1.7841x; 1.7841x over previous
#include <cuda_runtime.h>
#include <math.h>
#include <stdint.h>

#define NTOK   2048
#define DMODEL 256
#define DFF    1024
#define NHEAD  8
#define DHEAD  32
#define KWIN   5
#define NNBR   125   // 5*5*5

// ---------------- scratch (device globals; no allocations allowed) ----------
__device__ float g_q [NTOK * DMODEL];
__device__ float g_k [NTOK * DMODEL];
__device__ float g_v [NTOK * DMODEL];
__device__ float g_at[NTOK * DMODEL];
__device__ float g_h [NTOK * DMODEL];
__device__ float g_fa[NTOK * DFF];
__device__ float g_rs1[NTOK];
__device__ float g_ssp[16 * NTOK];  // per-row sumsq partials of h (16 col-slices)

// ---------------- helpers ----------------------------------------------------
__device__ __forceinline__ void mma_tf32(float d[4], const uint32_t a[4], const uint32_t b[2]) {
    asm volatile(
        "mma.sync.aligned.m16n8k8.row.col.f32.tf32.tf32.f32 "
        "{%0,%1,%2,%3},{%4,%5,%6,%7},{%8,%9},{%0,%1,%2,%3};"
        : "+f"(d[0]), "+f"(d[1]), "+f"(d[2]), "+f"(d[3])
        : "r"(a[0]), "r"(a[1]), "r"(a[2]), "r"(a[3]), "r"(b[0]), "r"(b[1]));
}

__device__ __forceinline__ void cp_async16(void* smem_dst, const void* gsrc) {
    uint32_t s = (uint32_t)__cvta_generic_to_shared(smem_dst);
    asm volatile("cp.async.cg.shared.global [%0], [%1], 16;" :: "r"(s), "l"(gsrc));
}
__device__ __forceinline__ void cp_commit() { asm volatile("cp.async.commit_group;"); }

#define ASTR 36   // A smem row stride: frag banks = 4g+tig, conflict-free
#define BSTR 68   // B smem row stride: frag banks = 4tig+g, conflict-free

// ---------------- RMS scale: one warp per token ------------------------------
__global__ __launch_bounds__(256) void rms_scale_k(const float* __restrict__ x,
                                                   float* __restrict__ rscale) {
    const int warp = threadIdx.x >> 5;
    const int lane = threadIdx.x & 31;
    const int token = blockIdx.x * 8 + warp;
    const float4 a = *(const float4*)&x[(size_t)token * DMODEL + lane * 4];
    const float4 b = *(const float4*)&x[(size_t)token * DMODEL + 128 + lane * 4];
    float s = a.x * a.x + a.y * a.y + a.z * a.z + a.w * a.w
            + b.x * b.x + b.y * b.y + b.z * b.z + b.w * b.w;
    #pragma unroll
    for (int o = 16; o; o >>= 1) s += __shfl_xor_sync(0xffffffffu, s, o);
    if (lane == 0) rscale[token] = rsqrtf(s * (1.0f / DMODEL) + 1e-6f);
}

// ---------------- TF32 GEMM v6: 32x64x32 tiles, 256 thr (8 warps, 2x4) ------
// Warp tile 16x16. cp.async double-buffered. Optional fused RMSNorm on A.
// Optional sumsq-partial output (16 col-slices). grid.z selects QKV triple.
__global__ __launch_bounds__(256) void gemm_v6(
    const float* __restrict__ A,
    const float* __restrict__ rs, const float* __restrict__ nw,
    const float* __restrict__ B0, const float* __restrict__ B1, const float* __restrict__ B2,
    const float* __restrict__ bias0, const float* __restrict__ bias1, const float* __restrict__ bias2,
    const float* __restrict__ res,
    float* __restrict__ C0, float* __restrict__ C1, float* __restrict__ C2,
    float* __restrict__ ssp,
    int N, int K) {

    const int z = blockIdx.z;
    const float* B    = (z == 0) ? B0    : (z == 1) ? B1    : B2;
    const float* bias = (z == 0) ? bias0 : (z == 1) ? bias1 : bias2;
    float*       C    = (z == 0) ? C0    : (z == 1) ? C1    : C2;

    __shared__ float As[2][32 * ASTR];
    __shared__ float Bs[2][32 * BSTR];

    const int tid  = threadIdx.x;
    const int warp = tid >> 5;
    const int lane = tid & 31;
    const int g    = lane >> 2;
    const int tig  = lane & 3;
    const int warpRow = (warp & 1) * 16;    // 2 warp-rows
    const int warpCol = (warp >> 1) * 16;   // 4 warp-cols, 16 wide
    const int bm = blockIdx.y * 32;
    const int bn = blockIdx.x * 64;

    float acc[2][4];
    #pragma unroll
    for (int nt = 0; nt < 2; nt++)
        #pragma unroll
        for (int i = 0; i < 4; i++) acc[nt][i] = 0.f;

    const int nkt = K >> 5;

    auto load_tile = [&](int buf, int k0) {
        {   // A: 256 float4 chunks, one per thread
            const int row = tid >> 3, kc = (tid & 7) * 4;
            if (rs) {
                const float4 xv = *(const float4*)&A[(size_t)(bm + row) * K + k0 + kc];
                const float4 wv = *(const float4*)&nw[k0 + kc];
                const float sc = rs[bm + row];
                float4 r;
                r.x = xv.x * sc * wv.x; r.y = xv.y * sc * wv.y;
                r.z = xv.z * sc * wv.z; r.w = xv.w * sc * wv.w;
                *(float4*)&As[buf][row * ASTR + kc] = r;
            } else {
                cp_async16(&As[buf][row * ASTR + kc], &A[(size_t)(bm + row) * K + k0 + kc]);
            }
        }
        #pragma unroll
        for (int j = 0; j < 2; j++) {   // B: 512 float4 chunks
            const int c = tid + 256 * j;
            const int row = c >> 4, nc = (c & 15) * 4;
            cp_async16(&Bs[buf][row * BSTR + nc], &B[(size_t)(k0 + row) * N + bn + nc]);
        }
        cp_commit();
    };

    load_tile(0, 0);

    for (int kt = 0; kt < nkt; kt++) {
        const int buf = kt & 1;
        if (kt + 1 < nkt) load_tile(buf ^ 1, (kt + 1) * 32);
        if (kt + 1 < nkt) asm volatile("cp.async.wait_group 1;");
        else              asm volatile("cp.async.wait_group 0;");
        __syncthreads();

        #pragma unroll
        for (int s = 0; s < 4; s++) {
            uint32_t a[4], b[2][2];
            const int r0 = warpRow + g;
            a[0] = __float_as_uint(As[buf][r0 * ASTR + 8 * s + tig]);
            a[1] = __float_as_uint(As[buf][(r0 + 8) * ASTR + 8 * s + tig]);
            a[2] = __float_as_uint(As[buf][r0 * ASTR + 8 * s + 4 + tig]);
            a[3] = __float_as_uint(As[buf][(r0 + 8) * ASTR + 8 * s + 4 + tig]);
            #pragma unroll
            for (int nt = 0; nt < 2; nt++) {
                const int c = warpCol + nt * 8 + g;
                b[nt][0] = __float_as_uint(Bs[buf][(8 * s + tig) * BSTR + c]);
                b[nt][1] = __float_as_uint(Bs[buf][(8 * s + 4 + tig) * BSTR + c]);
            }
            #pragma unroll
            for (int nt = 0; nt < 2; nt++) mma_tf32(acc[nt], a, b[nt]);
        }
        __syncthreads();
    }

    // epilogue (+optional per-row sumsq partials for the next rmsnorm)
    const int r0 = bm + warpRow + g;
    const int r1 = r0 + 8;
    float s0 = 0.f, s1 = 0.f;
    #pragma unroll
    for (int nt = 0; nt < 2; nt++) {
        const int col = bn + warpCol + nt * 8 + 2 * tig;
        float b0 = 0.f, b1 = 0.f;
        if (bias) { b0 = bias[col]; b1 = bias[col + 1]; }
        float2 o0 = make_float2(acc[nt][0] + b0, acc[nt][1] + b1);
        float2 o1 = make_float2(acc[nt][2] + b0, acc[nt][3] + b1);
        if (res) {
            const float2 q0 = *(const float2*)&res[(size_t)r0 * N + col];
            const float2 q1 = *(const float2*)&res[(size_t)r1 * N + col];
            o0.x += q0.x; o0.y += q0.y;
            o1.x += q1.x; o1.y += q1.y;
        }
        s0 += o0.x * o0.x + o0.y * o0.y;
        s1 += o1.x * o1.x + o1.y * o1.y;
        *(float2*)&C[(size_t)r0 * N + col] = o0;
        *(float2*)&C[(size_t)r1 * N + col] = o1;
    }
    if (ssp) {
        s0 += __shfl_xor_sync(0xffffffffu, s0, 1);
        s0 += __shfl_xor_sync(0xffffffffu, s0, 2);
        s1 += __shfl_xor_sync(0xffffffffu, s1, 1);
        s1 += __shfl_xor_sync(0xffffffffu, s1, 2);
        if (tig == 0) {
            const int p = blockIdx.x * 4 + (warp >> 1);   // 0..15 distinct col slices
            ssp[p * NTOK + r0] = s0;
            ssp[p * NTOK + r1] = s1;
        }
    }
}

// ---------------- gate GEMM v6: silu(A'@W1)*(A'@W2), 8 warps -----------------
// A' = rmsnorm(A) with scale rebuilt from 16 sumsq partials.
__global__ __launch_bounds__(256) void gemm_gate_v6(
    const float* __restrict__ A,
    const float* __restrict__ ssp, const float* __restrict__ nw,
    const float* __restrict__ W1, const float* __restrict__ W2,
    float* __restrict__ C, int N, int K) {

    __shared__ float As [2][32 * ASTR];
    __shared__ float B1s[2][32 * BSTR];
    __shared__ float B2s[2][32 * BSTR];
    __shared__ float rsc[32];

    const int tid  = threadIdx.x;
    const int warp = tid >> 5;
    const int lane = tid & 31;
    const int g    = lane >> 2;
    const int tig  = lane & 3;
    const int warpRow = (warp & 1) * 16;
    const int warpCol = (warp >> 1) * 16;
    const int bm = blockIdx.y * 32;
    const int bn = blockIdx.x * 64;

    if (tid < 32) {
        const int row = bm + tid;
        float s = 0.f;
        #pragma unroll
        for (int p = 0; p < 16; p++) s += ssp[p * NTOK + row];
        rsc[tid] = rsqrtf(s * (1.0f / DMODEL) + 1e-6f);
    }
    __syncthreads();

    float acc1[2][4], acc2[2][4];
    #pragma unroll
    for (int nt = 0; nt < 2; nt++)
        #pragma unroll
        for (int i = 0; i < 4; i++) { acc1[nt][i] = 0.f; acc2[nt][i] = 0.f; }

    const int nkt = K >> 5;

    auto load_tile = [&](int buf, int k0) {
        {   // A scaled: 256 float4 chunks
            const int row = tid >> 3, kc = (tid & 7) * 4;
            const float4 xv = *(const float4*)&A[(size_t)(bm + row) * K + k0 + kc];
            const float4 wv = *(const float4*)&nw[k0 + kc];
            const float sc = rsc[row];
            float4 r;
            r.x = xv.x * sc * wv.x; r.y = xv.y * sc * wv.y;
            r.z = xv.z * sc * wv.z; r.w = xv.w * sc * wv.w;
            *(float4*)&As[buf][row * ASTR + kc] = r;
        }
        #pragma unroll
        for (int j = 0; j < 2; j++) {
            const int c = tid + 256 * j;
            const int row = c >> 4, nc = (c & 15) * 4;
            const size_t off = (size_t)(k0 + row) * N + bn + nc;
            cp_async16(&B1s[buf][row * BSTR + nc], &W1[off]);
            cp_async16(&B2s[buf][row * BSTR + nc], &W2[off]);
        }
        cp_commit();
    };

    load_tile(0, 0);

    for (int kt = 0; kt < nkt; kt++) {
        const int buf = kt & 1;
        if (kt + 1 < nkt) load_tile(buf ^ 1, (kt + 1) * 32);
        if (kt + 1 < nkt) asm volatile("cp.async.wait_group 1;");
        else              asm volatile("cp.async.wait_group 0;");
        __syncthreads();

        #pragma unroll
        for (int s = 0; s < 4; s++) {
            uint32_t a[4], b1[2][2], b2[2][2];
            const int r0 = warpRow + g;
            a[0] = __float_as_uint(As[buf][r0 * ASTR + 8 * s + tig]);
            a[1] = __float_as_uint(As[buf][(r0 + 8) * ASTR + 8 * s + tig]);
            a[2] = __float_as_uint(As[buf][r0 * ASTR + 8 * s + 4 + tig]);
            a[3] = __float_as_uint(As[buf][(r0 + 8) * ASTR + 8 * s + 4 + tig]);
            #pragma unroll
            for (int nt = 0; nt < 2; nt++) {
                const int c = warpCol + nt * 8 + g;
                b1[nt][0] = __float_as_uint(B1s[buf][(8 * s + tig) * BSTR + c]);
                b1[nt][1] = __float_as_uint(B1s[buf][(8 * s + 4 + tig) * BSTR + c]);
                b2[nt][0] = __float_as_uint(B2s[buf][(8 * s + tig) * BSTR + c]);
                b2[nt][1] = __float_as_uint(B2s[buf][(8 * s + 4 + tig) * BSTR + c]);
            }
            #pragma unroll
            for (int nt = 0; nt < 2; nt++) {
                mma_tf32(acc1[nt], a, b1[nt]);
                mma_tf32(acc2[nt], a, b2[nt]);
            }
        }
        __syncthreads();
    }

    const int r0 = bm + warpRow + g;
    const int r1 = r0 + 8;
    #pragma unroll
    for (int nt = 0; nt < 2; nt++) {
        const int col = bn + warpCol + nt * 8 + 2 * tig;
        #pragma unroll
        for (int half = 0; half < 2; half++) {
            const int row = (half == 0) ? r0 : r1;
            const float a0 = acc1[nt][half * 2 + 0];
            const float a1 = acc1[nt][half * 2 + 1];
            float2 o;
            o.x = a0 / (1.f + __expf(-a0)) * acc2[nt][half * 2 + 0];
            o.y = a1 / (1.f + __expf(-a1)) * acc2[nt][half * 2 + 1];
            *(float2*)&C[(size_t)row * N + col] = o;
        }
    }
}

// ---------------- NA3D attention: smem-tiled ---------------------------------
__global__ __launch_bounds__(512) void na3d_k(
    const float* __restrict__ q, const float* __restrict__ k,
    const float* __restrict__ v, float* __restrict__ out) {

    __shared__ float smk[320 * 32];
    __shared__ int   nbase[128];

    const int tile = blockIdx.x;
    const int head = blockIdx.y;
    const int t  = tile >> 4;
    const int hh = (tile >> 2) & 3;
    const int ww = tile & 3;
    const int tile_h0 = hh * 4, tile_w0 = ww * 4;
    const int h_base = min(max(tile_h0 - 2, 0), 8);
    const int w_base = min(max(tile_w0 - 2, 0), 8);

    const int tid  = threadIdx.x;
    const int warp = tid >> 5;
    const int lane = tid & 31;
    const int g    = lane >> 3;
    const int sub  = lane & 7;

    if (tid < 128) {
        const int m = tid;
        int val;
        if (m < NNBR) {
            const int mt = m / 25;
            const int mh = (m / 5) % 5;
            const int mw = m % 5;
            val = (mt * 64 + mh * 8 + mw) | (mt << 16);
        } else {
            val = (-8) << 16;
        }
        nbase[tid] = val;
    }

    const int h = tile_h0 + (warp >> 2);
    const int w = tile_w0 + (warp & 3);
    const int token = (t * 16 + h) * 16 + w;
    const int hoff = min(max(h - 2, 0), 11) - h_base;
    const int woff = min(max(w - 2, 0), 11) - w_base;
    const int sbase = hoff * 8 + woff;

    #pragma unroll
    for (int j = 0; j < 5; j++) {
        const int c = tid + 512 * j;
        const int slot = c >> 3, s8 = c & 7;
        const int tl = slot >> 6, rem = slot & 63;
        const int tn = max(t - 4 + tl, 0);
        const int hn = h_base + (rem >> 3), wn = w_base + (rem & 7);
        const float4 kv = *(const float4*)&k[(size_t)((tn * 16 + hn) * 16 + wn) * DMODEL + head * DHEAD + s8 * 4];
        *(float4*)&smk[slot * 32 + s8 * 4] = kv;
    }
    const float4 q4 = *(const float4*)&q[(size_t)token * DMODEL + head * DHEAD + sub * 4];
    __syncthreads();

    float lg[32];
    const float scale = 0.17677669529663687f;
    #pragma unroll
    for (int i = 0; i < 32; i++) {
        const int m   = i * 4 + g;
        const int val = nbase[m];
        const int slot = (val & 0xFFFF) + sbase;
        const int mt   = val >> 16;
        const float4 kv = *(const float4*)&smk[slot * 32 + sub * 4];
        float d = q4.x * kv.x + q4.y * kv.y + q4.z * kv.z + q4.w * kv.w;
        d += __shfl_xor_sync(0xffffffffu, d, 1);
        d += __shfl_xor_sync(0xffffffffu, d, 2);
        d += __shfl_xor_sync(0xffffffffu, d, 4);
        lg[i] = (t - 4 + mt >= 0) ? d * scale : -INFINITY;
    }

    float mx = -INFINITY;
    #pragma unroll
    for (int i = 0; i < 32; i++) mx = fmaxf(mx, lg[i]);
    #pragma unroll
    for (int o = 16; o; o >>= 1) mx = fmaxf(mx, __shfl_xor_sync(0xffffffffu, mx, o));
    float sum = 0.f;
    #pragma unroll
    for (int i = 0; i < 32; i++) { lg[i] = __expf(lg[i] - mx); sum += lg[i]; }
    sum += __shfl_xor_sync(0xffffffffu, sum, 8);
    sum += __shfl_xor_sync(0xffffffffu, sum, 16);
    const float inv = 1.f / sum;

    __syncthreads();
    #pragma unroll
    for (int j = 0; j < 5; j++) {
        const int c = tid + 512 * j;
        const int slot = c >> 3, s8 = c & 7;
        const int tl = slot >> 6, rem = slot & 63;
        const int tn = max(t - 4 + tl, 0);
        const int hn = h_base + (rem >> 3), wn = w_base + (rem & 7);
        const float4 vv = *(const float4*)&v[(size_t)((tn * 16 + hn) * 16 + wn) * DMODEL + head * DHEAD + s8 * 4];
        *(float4*)&smk[slot * 32 + s8 * 4] = vv;
    }
    __syncthreads();

    float4 acc = make_float4(0.f, 0.f, 0.f, 0.f);
    #pragma unroll
    for (int i = 0; i < 32; i++) {
        const int m    = i * 4 + g;
        const int slot = (nbase[m] & 0xFFFF) + sbase;
        const float4 vv = *(const float4*)&smk[slot * 32 + sub * 4];
        const float p = lg[i];
        acc.x = fmaf(p, vv.x, acc.x);
        acc.y = fmaf(p, vv.y, acc.y);
        acc.z = fmaf(p, vv.z, acc.z);
        acc.w = fmaf(p, vv.w, acc.w);
    }
    #pragma unroll
    for (int o = 8; o <= 16; o <<= 1) {
        acc.x += __shfl_xor_sync(0xffffffffu, acc.x, o);
        acc.y += __shfl_xor_sync(0xffffffffu, acc.y, o);
        acc.z += __shfl_xor_sync(0xffffffffu, acc.z, o);
        acc.w += __shfl_xor_sync(0xffffffffu, acc.w, o);
    }
    if (g == 0) {
        float4 o4 = make_float4(acc.x * inv, acc.y * inv, acc.z * inv, acc.w * inv);
        *(float4*)&out[(size_t)token * DMODEL + head * DHEAD + sub * 4] = o4;
    }
}

// ---------------- launch ------------------------------------------------------
extern "C" void kernel_launch(void* const* d_in, const int* in_sizes, int n_in,
                              void* d_out, int out_size) {
    const float* x   = (const float*)d_in[0];
    const float* n1w = (const float*)d_in[1];
    const float* n2w = (const float*)d_in[2];
    const float* wq  = (const float*)d_in[3];
    const float* bq  = (const float*)d_in[4];
    const float* wk  = (const float*)d_in[5];
    const float* bk  = (const float*)d_in[6];
    const float* wv  = (const float*)d_in[7];
    const float* bv  = (const float*)d_in[8];
    const float* wo  = (const float*)d_in[9];
    const float* bo  = (const float*)d_in[10];
    const float* w1  = (const float*)d_in[11];
    const float* w2  = (const float*)d_in[12];
    const float* w3  = (const float*)d_in[13];
    float* out = (float*)d_out;

    float *p_q, *p_k, *p_v, *p_at, *p_h, *p_fa, *p_rs1, *p_ssp;
    cudaGetSymbolAddress((void**)&p_q,  g_q);
    cudaGetSymbolAddress((void**)&p_k,  g_k);
    cudaGetSymbolAddress((void**)&p_v,  g_v);
    cudaGetSymbolAddress((void**)&p_at, g_at);
    cudaGetSymbolAddress((void**)&p_h,  g_h);
    cudaGetSymbolAddress((void**)&p_fa, g_fa);
    cudaGetSymbolAddress((void**)&p_rs1, g_rs1);
    cudaGetSymbolAddress((void**)&p_ssp, g_ssp);

    const dim3 blk(256);

    // 1) rscale1 = rms scale of x
    rms_scale_k<<<NTOK / 8, 256>>>(x, p_rs1);

    // 2) q,k,v = rmsnorm(x) @ {wq,wk,wv} + bias
    gemm_v6<<<dim3(DMODEL / 64, NTOK / 32, 3), blk>>>(
        x, p_rs1, n1w, wq, wk, wv, bq, bk, bv, nullptr,
        p_q, p_k, p_v, nullptr, DMODEL, DMODEL);

    // 3) neighborhood attention
    na3d_k<<<dim3(128, NHEAD), 512>>>(p_q, p_k, p_v, p_at);

    // 4) h = x + attn @ wo + bo   (+ per-row sumsq partials of h)
    gemm_v6<<<dim3(DMODEL / 64, NTOK / 32, 1), blk>>>(
        p_at, nullptr, nullptr, wo, nullptr, nullptr, bo, nullptr, nullptr, x,
        p_h, nullptr, nullptr, p_ssp, DMODEL, DMODEL);

    // 5) fa = silu(rmsnorm(h)@w1) * (rmsnorm(h)@w2)  (rms scale from partials)
    gemm_gate_v6<<<dim3(DFF / 64, NTOK / 32), blk>>>(
        p_h, p_ssp, n2w, w1, w2, p_fa, DFF, DMODEL);

    // 6) out = h + fa @ w3
    gemm_v6<<<dim3(DMODEL / 64, NTOK / 32, 1), blk>>>(
        p_fa, nullptr, nullptr, w3, nullptr, nullptr, nullptr, nullptr, nullptr, p_h,
        out, nullptr, nullptr, nullptr, DMODEL, DFF);
}

// round 8
// speedup vs baseline: 2.2672x; 1.2708x over previous
#include <cuda_runtime.h>
#include <math.h>
#include <stdint.h>

#define NTOK   2048
#define DMODEL 256
#define DFF    1024
#define NHEAD  8
#define DHEAD  32
#define KWIN   5
#define NNBR   125   // 5*5*5

// ---------------- scratch (device globals; no allocations allowed) ----------
__device__ float g_q [NTOK * DMODEL];
__device__ float g_k [NTOK * DMODEL];
__device__ float g_v [NTOK * DMODEL];
__device__ float g_at[NTOK * DMODEL];
__device__ float g_h [NTOK * DMODEL];
__device__ float g_fa[NTOK * DFF];
__device__ float g_rs1[NTOK];
__device__ float g_ssp[8 * NTOK];   // per-row sumsq partials of h (8 col-slices)

// ---------------- helpers ----------------------------------------------------
__device__ __forceinline__ void mma_tf32(float d[4], const uint32_t a[4], const uint32_t b[2]) {
    asm volatile(
        "mma.sync.aligned.m16n8k8.row.col.f32.tf32.tf32.f32 "
        "{%0,%1,%2,%3},{%4,%5,%6,%7},{%8,%9},{%0,%1,%2,%3};"
        : "+f"(d[0]), "+f"(d[1]), "+f"(d[2]), "+f"(d[3])
        : "r"(a[0]), "r"(a[1]), "r"(a[2]), "r"(a[3]), "r"(b[0]), "r"(b[1]));
}

__device__ __forceinline__ void cp_async16(void* smem_dst, const void* gsrc) {
    uint32_t s = (uint32_t)__cvta_generic_to_shared(smem_dst);
    asm volatile("cp.async.cg.shared.global [%0], [%1], 16;" :: "r"(s), "l"(gsrc));
}
__device__ __forceinline__ void cp_commit() { asm volatile("cp.async.commit_group;"); }

#define ASTR 36   // A frag banks: (36g+tig)%32 = 4g+tig -> permutation, conflict-free
#define BSTR 72   // B frag banks: (72tig+g)%32 = 8tig+g -> permutation, conflict-free
#define NSTG 3    // pipeline stages

// ---------------- RMS scale: one warp per token ------------------------------
__global__ __launch_bounds__(256) void rms_scale_k(const float* __restrict__ x,
                                                   float* __restrict__ rscale) {
    const int warp = threadIdx.x >> 5;
    const int lane = threadIdx.x & 31;
    const int token = blockIdx.x * 8 + warp;
    const float4 a = *(const float4*)&x[(size_t)token * DMODEL + lane * 4];
    const float4 b = *(const float4*)&x[(size_t)token * DMODEL + 128 + lane * 4];
    float s = a.x * a.x + a.y * a.y + a.z * a.z + a.w * a.w
            + b.x * b.x + b.y * b.y + b.z * b.z + b.w * b.w;
    #pragma unroll
    for (int o = 16; o; o >>= 1) s += __shfl_xor_sync(0xffffffffu, s, o);
    if (lane == 0) rscale[token] = rsqrtf(s * (1.0f / DMODEL) + 1e-6f);
}

// ---------------- TF32 GEMM v7: 32x64x32, 128 thr, 3-stage, conflict-free ----
// SCALED: A_eff[m,k] = A[m,k]*rs[m]*nw[k], applied at fragment-load time.
// Optional ssp output (8 col-slices of per-row sumsq). grid.z selects triple.
template<bool SCALED>
__global__ __launch_bounds__(128) void gemm_v7(
    const float* __restrict__ A,
    const float* __restrict__ rs, const float* __restrict__ nw,
    const float* __restrict__ B0, const float* __restrict__ B1, const float* __restrict__ B2,
    const float* __restrict__ bias0, const float* __restrict__ bias1, const float* __restrict__ bias2,
    const float* __restrict__ res,
    float* __restrict__ C0, float* __restrict__ C1, float* __restrict__ C2,
    float* __restrict__ ssp,
    int N, int K) {

    const int z = blockIdx.z;
    const float* B    = (z == 0) ? B0    : (z == 1) ? B1    : B2;
    const float* bias = (z == 0) ? bias0 : (z == 1) ? bias1 : bias2;
    float*       C    = (z == 0) ? C0    : (z == 1) ? C1    : C2;

    __shared__ float As[NSTG][32 * ASTR];
    __shared__ float Bs[NSTG][32 * BSTR];
    __shared__ float nws[DMODEL];
    __shared__ float rsc[32];

    const int tid  = threadIdx.x;
    const int warp = tid >> 5;
    const int lane = tid & 31;
    const int g    = lane >> 2;
    const int tig  = lane & 3;
    const int warpRow = (warp & 1) * 16;    // 2 warp-rows
    const int warpCol = (warp >> 1) * 32;   // 2 warp-cols, 32 wide
    const int bm = blockIdx.y * 32;
    const int bn = blockIdx.x * 64;

    float sc0 = 1.f, sc1 = 1.f;
    if (SCALED) {
        for (int i = tid * 4; i < K; i += 512)
            *(float4*)&nws[i] = *(const float4*)&nw[i];
        if (tid < 32) rsc[tid] = rs[bm + tid];
        __syncthreads();
        sc0 = rsc[warpRow + g];
        sc1 = rsc[warpRow + g + 8];
    }

    float acc[4][4];
    #pragma unroll
    for (int nt = 0; nt < 4; nt++)
        #pragma unroll
        for (int i = 0; i < 4; i++) acc[nt][i] = 0.f;

    const int nkt = K >> 5;

    auto load_tile = [&](int st, int k0) {
        #pragma unroll
        for (int j = 0; j < 2; j++) {          // A: 256 float4 chunks
            const int c = tid + 128 * j;
            const int row = c >> 3, kc = (c & 7) * 4;
            cp_async16(&As[st][row * ASTR + kc], &A[(size_t)(bm + row) * K + k0 + kc]);
        }
        #pragma unroll
        for (int j = 0; j < 4; j++) {          // B: 512 float4 chunks
            const int c = tid + 128 * j;
            const int row = c >> 4, nc = (c & 15) * 4;
            cp_async16(&Bs[st][row * BSTR + nc], &B[(size_t)(k0 + row) * N + bn + nc]);
        }
        cp_commit();
    };

    load_tile(0, 0);
    load_tile(1, 32);

    for (int kt = 0; kt < nkt; kt++) {
        const int st = kt % NSTG;
        if (kt + 2 < nkt) load_tile((kt + 2) % NSTG, (kt + 2) * 32);
        if (kt + 2 < nkt)      asm volatile("cp.async.wait_group 2;");
        else if (kt + 1 < nkt) asm volatile("cp.async.wait_group 1;");
        else                   asm volatile("cp.async.wait_group 0;");
        __syncthreads();

        const float* Ab = As[st];
        const float* Bb = Bs[st];
        const int kb = kt * 32;
        #pragma unroll
        for (int s = 0; s < 4; s++) {
            const int r0 = warpRow + g;
            float a0 = Ab[r0 * ASTR + 8 * s + tig];
            float a1 = Ab[(r0 + 8) * ASTR + 8 * s + tig];
            float a2 = Ab[r0 * ASTR + 8 * s + 4 + tig];
            float a3 = Ab[(r0 + 8) * ASTR + 8 * s + 4 + tig];
            if (SCALED) {
                const float w0 = nws[kb + 8 * s + tig];
                const float w1 = nws[kb + 8 * s + 4 + tig];
                a0 *= sc0 * w0; a1 *= sc1 * w0; a2 *= sc0 * w1; a3 *= sc1 * w1;
            }
            uint32_t ua[4] = {__float_as_uint(a0), __float_as_uint(a1),
                              __float_as_uint(a2), __float_as_uint(a3)};
            uint32_t b[4][2];
            #pragma unroll
            for (int nt = 0; nt < 4; nt++) {
                const int c = warpCol + nt * 8 + g;
                b[nt][0] = __float_as_uint(Bb[(8 * s + tig) * BSTR + c]);
                b[nt][1] = __float_as_uint(Bb[(8 * s + 4 + tig) * BSTR + c]);
            }
            #pragma unroll
            for (int nt = 0; nt < 4; nt++) mma_tf32(acc[nt], ua, b[nt]);
        }
        __syncthreads();
    }

    // epilogue (+optional per-row sumsq partials for the next rmsnorm)
    const int r0 = bm + warpRow + g;
    const int r1 = r0 + 8;
    float s0 = 0.f, s1 = 0.f;
    #pragma unroll
    for (int nt = 0; nt < 4; nt++) {
        const int col = bn + warpCol + nt * 8 + 2 * tig;
        float b0 = 0.f, b1 = 0.f;
        if (bias) { b0 = bias[col]; b1 = bias[col + 1]; }
        float2 o0 = make_float2(acc[nt][0] + b0, acc[nt][1] + b1);
        float2 o1 = make_float2(acc[nt][2] + b0, acc[nt][3] + b1);
        if (res) {
            const float2 q0 = *(const float2*)&res[(size_t)r0 * N + col];
            const float2 q1 = *(const float2*)&res[(size_t)r1 * N + col];
            o0.x += q0.x; o0.y += q0.y;
            o1.x += q1.x; o1.y += q1.y;
        }
        s0 += o0.x * o0.x + o0.y * o0.y;
        s1 += o1.x * o1.x + o1.y * o1.y;
        *(float2*)&C[(size_t)r0 * N + col] = o0;
        *(float2*)&C[(size_t)r1 * N + col] = o1;
    }
    if (ssp) {
        s0 += __shfl_xor_sync(0xffffffffu, s0, 1);
        s0 += __shfl_xor_sync(0xffffffffu, s0, 2);
        s1 += __shfl_xor_sync(0xffffffffu, s1, 1);
        s1 += __shfl_xor_sync(0xffffffffu, s1, 2);
        if (tig == 0) {
            const int p = blockIdx.x * 2 + (warp >> 1);   // 0..7 distinct col slices
            ssp[p * NTOK + r0] = s0;
            ssp[p * NTOK + r1] = s1;
        }
    }
}

// ---------------- gate GEMM v7: silu(A'@W1)*(A'@W2), 3-stage, dual B ---------
// A' = rmsnorm(A); row scale rebuilt from 8 sumsq partials. 32x64 tile.
__global__ __launch_bounds__(128) void gate_v7(
    const float* __restrict__ A,
    const float* __restrict__ ssp, const float* __restrict__ nw,
    const float* __restrict__ W1, const float* __restrict__ W2,
    float* __restrict__ C, int N, int K) {

    extern __shared__ float dsm[];
    float* nws = dsm;                       // 256
    float* rsc = dsm + DMODEL;              // 32
    float* Asm = rsc + 32;                  // NSTG * 32*ASTR
    float* B1m = Asm + NSTG * 32 * ASTR;    // NSTG * 32*BSTR
    float* B2m = B1m + NSTG * 32 * BSTR;    // NSTG * 32*BSTR

    const int tid  = threadIdx.x;
    const int warp = tid >> 5;
    const int lane = tid & 31;
    const int g    = lane >> 2;
    const int tig  = lane & 3;
    const int warpRow = (warp & 1) * 16;
    const int warpCol = (warp >> 1) * 32;
    const int bm = blockIdx.y * 32;
    const int bn = blockIdx.x * 64;

    for (int i = tid * 4; i < K; i += 512)
        *(float4*)&nws[i] = *(const float4*)&nw[i];
    if (tid < 32) {
        const int row = bm + tid;
        float s = 0.f;
        #pragma unroll
        for (int p = 0; p < 8; p++) s += ssp[p * NTOK + row];
        rsc[tid] = rsqrtf(s * (1.0f / DMODEL) + 1e-6f);
    }
    __syncthreads();
    const float sc0 = rsc[warpRow + g];
    const float sc1 = rsc[warpRow + g + 8];

    float acc1[4][4], acc2[4][4];
    #pragma unroll
    for (int nt = 0; nt < 4; nt++)
        #pragma unroll
        for (int i = 0; i < 4; i++) { acc1[nt][i] = 0.f; acc2[nt][i] = 0.f; }

    const int nkt = K >> 5;

    auto load_tile = [&](int st, int k0) {
        float* Ad  = Asm + st * 32 * ASTR;
        float* B1d = B1m + st * 32 * BSTR;
        float* B2d = B2m + st * 32 * BSTR;
        #pragma unroll
        for (int j = 0; j < 2; j++) {
            const int c = tid + 128 * j;
            const int row = c >> 3, kc = (c & 7) * 4;
            cp_async16(&Ad[row * ASTR + kc], &A[(size_t)(bm + row) * K + k0 + kc]);
        }
        #pragma unroll
        for (int j = 0; j < 4; j++) {
            const int c = tid + 128 * j;
            const int row = c >> 4, nc = (c & 15) * 4;
            const size_t off = (size_t)(k0 + row) * N + bn + nc;
            cp_async16(&B1d[row * BSTR + nc], &W1[off]);
            cp_async16(&B2d[row * BSTR + nc], &W2[off]);
        }
        cp_commit();
    };

    load_tile(0, 0);
    load_tile(1, 32);

    for (int kt = 0; kt < nkt; kt++) {
        const int st = kt % NSTG;
        if (kt + 2 < nkt) load_tile((kt + 2) % NSTG, (kt + 2) * 32);
        if (kt + 2 < nkt)      asm volatile("cp.async.wait_group 2;");
        else if (kt + 1 < nkt) asm volatile("cp.async.wait_group 1;");
        else                   asm volatile("cp.async.wait_group 0;");
        __syncthreads();

        const float* Ab  = Asm + st * 32 * ASTR;
        const float* B1b = B1m + st * 32 * BSTR;
        const float* B2b = B2m + st * 32 * BSTR;
        const int kb = kt * 32;
        #pragma unroll
        for (int s = 0; s < 4; s++) {
            const int r0 = warpRow + g;
            float a0 = Ab[r0 * ASTR + 8 * s + tig];
            float a1 = Ab[(r0 + 8) * ASTR + 8 * s + tig];
            float a2 = Ab[r0 * ASTR + 8 * s + 4 + tig];
            float a3 = Ab[(r0 + 8) * ASTR + 8 * s + 4 + tig];
            const float w0 = nws[kb + 8 * s + tig];
            const float w1 = nws[kb + 8 * s + 4 + tig];
            a0 *= sc0 * w0; a1 *= sc1 * w0; a2 *= sc0 * w1; a3 *= sc1 * w1;
            uint32_t ua[4] = {__float_as_uint(a0), __float_as_uint(a1),
                              __float_as_uint(a2), __float_as_uint(a3)};
            uint32_t b1[4][2], b2[4][2];
            #pragma unroll
            for (int nt = 0; nt < 4; nt++) {
                const int c = warpCol + nt * 8 + g;
                b1[nt][0] = __float_as_uint(B1b[(8 * s + tig) * BSTR + c]);
                b1[nt][1] = __float_as_uint(B1b[(8 * s + 4 + tig) * BSTR + c]);
                b2[nt][0] = __float_as_uint(B2b[(8 * s + tig) * BSTR + c]);
                b2[nt][1] = __float_as_uint(B2b[(8 * s + 4 + tig) * BSTR + c]);
            }
            #pragma unroll
            for (int nt = 0; nt < 4; nt++) {
                mma_tf32(acc1[nt], ua, b1[nt]);
                mma_tf32(acc2[nt], ua, b2[nt]);
            }
        }
        __syncthreads();
    }

    const int r0 = bm + warpRow + g;
    const int r1 = r0 + 8;
    #pragma unroll
    for (int nt = 0; nt < 4; nt++) {
        const int col = bn + warpCol + nt * 8 + 2 * tig;
        #pragma unroll
        for (int half = 0; half < 2; half++) {
            const int row = (half == 0) ? r0 : r1;
            const float a0 = acc1[nt][half * 2 + 0];
            const float a1 = acc1[nt][half * 2 + 1];
            float2 o;
            o.x = a0 / (1.f + __expf(-a0)) * acc2[nt][half * 2 + 0];
            o.y = a1 / (1.f + __expf(-a1)) * acc2[nt][half * 2 + 1];
            *(float2*)&C[(size_t)row * N + col] = o;
        }
    }
}

// ---------------- NA3D attention: smem-tiled ---------------------------------
__global__ __launch_bounds__(512) void na3d_k(
    const float* __restrict__ q, const float* __restrict__ k,
    const float* __restrict__ v, float* __restrict__ out) {

    __shared__ float smk[320 * 32];
    __shared__ int   nbase[128];

    const int tile = blockIdx.x;
    const int head = blockIdx.y;
    const int t  = tile >> 4;
    const int hh = (tile >> 2) & 3;
    const int ww = tile & 3;
    const int tile_h0 = hh * 4, tile_w0 = ww * 4;
    const int h_base = min(max(tile_h0 - 2, 0), 8);
    const int w_base = min(max(tile_w0 - 2, 0), 8);

    const int tid  = threadIdx.x;
    const int warp = tid >> 5;
    const int lane = tid & 31;
    const int g    = lane >> 3;
    const int sub  = lane & 7;

    if (tid < 128) {
        const int m = tid;
        int val;
        if (m < NNBR) {
            const int mt = m / 25;
            const int mh = (m / 5) % 5;
            const int mw = m % 5;
            val = (mt * 64 + mh * 8 + mw) | (mt << 16);
        } else {
            val = (-8) << 16;
        }
        nbase[tid] = val;
    }

    const int h = tile_h0 + (warp >> 2);
    const int w = tile_w0 + (warp & 3);
    const int token = (t * 16 + h) * 16 + w;
    const int hoff = min(max(h - 2, 0), 11) - h_base;
    const int woff = min(max(w - 2, 0), 11) - w_base;
    const int sbase = hoff * 8 + woff;

    #pragma unroll
    for (int j = 0; j < 5; j++) {
        const int c = tid + 512 * j;
        const int slot = c >> 3, s8 = c & 7;
        const int tl = slot >> 6, rem = slot & 63;
        const int tn = max(t - 4 + tl, 0);
        const int hn = h_base + (rem >> 3), wn = w_base + (rem & 7);
        const float4 kv = *(const float4*)&k[(size_t)((tn * 16 + hn) * 16 + wn) * DMODEL + head * DHEAD + s8 * 4];
        *(float4*)&smk[slot * 32 + s8 * 4] = kv;
    }
    const float4 q4 = *(const float4*)&q[(size_t)token * DMODEL + head * DHEAD + sub * 4];
    __syncthreads();

    float lg[32];
    const float scale = 0.17677669529663687f;
    #pragma unroll
    for (int i = 0; i < 32; i++) {
        const int m   = i * 4 + g;
        const int val = nbase[m];
        const int slot = (val & 0xFFFF) + sbase;
        const int mt   = val >> 16;
        const float4 kv = *(const float4*)&smk[slot * 32 + sub * 4];
        float d = q4.x * kv.x + q4.y * kv.y + q4.z * kv.z + q4.w * kv.w;
        d += __shfl_xor_sync(0xffffffffu, d, 1);
        d += __shfl_xor_sync(0xffffffffu, d, 2);
        d += __shfl_xor_sync(0xffffffffu, d, 4);
        lg[i] = (t - 4 + mt >= 0) ? d * scale : -INFINITY;
    }

    float mx = -INFINITY;
    #pragma unroll
    for (int i = 0; i < 32; i++) mx = fmaxf(mx, lg[i]);
    #pragma unroll
    for (int o = 16; o; o >>= 1) mx = fmaxf(mx, __shfl_xor_sync(0xffffffffu, mx, o));
    float sum = 0.f;
    #pragma unroll
    for (int i = 0; i < 32; i++) { lg[i] = __expf(lg[i] - mx); sum += lg[i]; }
    sum += __shfl_xor_sync(0xffffffffu, sum, 8);
    sum += __shfl_xor_sync(0xffffffffu, sum, 16);
    const float inv = 1.f / sum;

    __syncthreads();
    #pragma unroll
    for (int j = 0; j < 5; j++) {
        const int c = tid + 512 * j;
        const int slot = c >> 3, s8 = c & 7;
        const int tl = slot >> 6, rem = slot & 63;
        const int tn = max(t - 4 + tl, 0);
        const int hn = h_base + (rem >> 3), wn = w_base + (rem & 7);
        const float4 vv = *(const float4*)&v[(size_t)((tn * 16 + hn) * 16 + wn) * DMODEL + head * DHEAD + s8 * 4];
        *(float4*)&smk[slot * 32 + s8 * 4] = vv;
    }
    __syncthreads();

    float4 acc = make_float4(0.f, 0.f, 0.f, 0.f);
    #pragma unroll
    for (int i = 0; i < 32; i++) {
        const int m    = i * 4 + g;
        const int slot = (nbase[m] & 0xFFFF) + sbase;
        const float4 vv = *(const float4*)&smk[slot * 32 + sub * 4];
        const float p = lg[i];
        acc.x = fmaf(p, vv.x, acc.x);
        acc.y = fmaf(p, vv.y, acc.y);
        acc.z = fmaf(p, vv.z, acc.z);
        acc.w = fmaf(p, vv.w, acc.w);
    }
    #pragma unroll
    for (int o = 8; o <= 16; o <<= 1) {
        acc.x += __shfl_xor_sync(0xffffffffu, acc.x, o);
        acc.y += __shfl_xor_sync(0xffffffffu, acc.y, o);
        acc.z += __shfl_xor_sync(0xffffffffu, acc.z, o);
        acc.w += __shfl_xor_sync(0xffffffffu, acc.w, o);
    }
    if (g == 0) {
        float4 o4 = make_float4(acc.x * inv, acc.y * inv, acc.z * inv, acc.w * inv);
        *(float4*)&out[(size_t)token * DMODEL + head * DHEAD + sub * 4] = o4;
    }
}

// ---------------- launch ------------------------------------------------------
extern "C" void kernel_launch(void* const* d_in, const int* in_sizes, int n_in,
                              void* d_out, int out_size) {
    const float* x   = (const float*)d_in[0];
    const float* n1w = (const float*)d_in[1];
    const float* n2w = (const float*)d_in[2];
    const float* wq  = (const float*)d_in[3];
    const float* bq  = (const float*)d_in[4];
    const float* wk  = (const float*)d_in[5];
    const float* bk  = (const float*)d_in[6];
    const float* wv  = (const float*)d_in[7];
    const float* bv  = (const float*)d_in[8];
    const float* wo  = (const float*)d_in[9];
    const float* bo  = (const float*)d_in[10];
    const float* w1  = (const float*)d_in[11];
    const float* w2  = (const float*)d_in[12];
    const float* w3  = (const float*)d_in[13];
    float* out = (float*)d_out;

    float *p_q, *p_k, *p_v, *p_at, *p_h, *p_fa, *p_rs1, *p_ssp;
    cudaGetSymbolAddress((void**)&p_q,  g_q);
    cudaGetSymbolAddress((void**)&p_k,  g_k);
    cudaGetSymbolAddress((void**)&p_v,  g_v);
    cudaGetSymbolAddress((void**)&p_at, g_at);
    cudaGetSymbolAddress((void**)&p_h,  g_h);
    cudaGetSymbolAddress((void**)&p_fa, g_fa);
    cudaGetSymbolAddress((void**)&p_rs1, g_rs1);
    cudaGetSymbolAddress((void**)&p_ssp, g_ssp);

    const int gate_smem = (DMODEL + 32 + NSTG * 32 * ASTR + 2 * NSTG * 32 * BSTR) * 4;
    cudaFuncSetAttribute(gate_v7, cudaFuncAttributeMaxDynamicSharedMemorySize, gate_smem);

    const dim3 blk(128);

    // 1) rscale1 = rms scale of x
    rms_scale_k<<<NTOK / 8, 256>>>(x, p_rs1);

    // 2) q,k,v = rmsnorm(x) @ {wq,wk,wv} + bias
    gemm_v7<true><<<dim3(DMODEL / 64, NTOK / 32, 3), blk>>>(
        x, p_rs1, n1w, wq, wk, wv, bq, bk, bv, nullptr,
        p_q, p_k, p_v, nullptr, DMODEL, DMODEL);

    // 3) neighborhood attention
    na3d_k<<<dim3(128, NHEAD), 512>>>(p_q, p_k, p_v, p_at);

    // 4) h = x + attn @ wo + bo   (+ per-row sumsq partials of h)
    gemm_v7<false><<<dim3(DMODEL / 64, NTOK / 32, 1), blk>>>(
        p_at, nullptr, nullptr, wo, nullptr, nullptr, bo, nullptr, nullptr, x,
        p_h, nullptr, nullptr, p_ssp, DMODEL, DMODEL);

    // 5) fa = silu(rmsnorm(h)@w1) * (rmsnorm(h)@w2)  (rms scale from partials)
    gate_v7<<<dim3(DFF / 64, NTOK / 32), blk, gate_smem>>>(
        p_h, p_ssp, n2w, w1, w2, p_fa, DFF, DMODEL);

    // 6) out = h + fa @ w3
    gemm_v7<false><<<dim3(DMODEL / 64, NTOK / 32, 1), blk>>>(
        p_fa, nullptr, nullptr, w3, nullptr, nullptr, nullptr, nullptr, nullptr, p_h,
        out, nullptr, nullptr, nullptr, DMODEL, DFF);
}